// round 15
// baseline (speedup 1.0000x reference)
#include <cuda_runtime.h>
#include <cuda_fp16.h>
#include <math.h>
#include <stdint.h>

#define BATCH  2
#define SEQ    2048
#define DM     1024
#define NHEADS 16
#define HD     64
#define MTOT   (BATCH * SEQ)   // 4096

// ---------------- scratch (static device globals; no runtime alloc) --------
__device__ __half g_xh [MTOT * DM];      // x, fp16
__device__ __half g_wh [4 * DM * DM];    // transposed weights [mat][N][K], fp16
__device__ __half g_qh [MTOT * DM];      // Q, PRESCALED by 0.125*log2(e)
__device__ __half g_kh [MTOT * DM];      // K [tok][dmodel]
__device__ __half g_vth[MTOT * DM];      // V transposed [b*h][d(64)][seq]
__device__ __half g_ctxh[MTOT * DM];     // attention output [tok][dmodel]

// ============================ helpers ======================================
__device__ __forceinline__ uint32_t h2u(float a, float b) {
    __half2 h = __floats2half2_rn(a, b);
    return *(uint32_t*)&h;
}
__device__ __forceinline__ uint32_t ex2h2(uint32_t x) {   // packed 2^x, fp16x2
    uint32_t r;
    asm("ex2.approx.f16x2 %0, %1;" : "=r"(r) : "r"(x));
    return r;
}
__device__ __forceinline__ uint32_t smem_u32(const void* p) {
    uint32_t a;
    asm("{ .reg .u64 t; cvta.to.shared.u64 t, %1; cvt.u32.u64 %0, t; }"
        : "=r"(a) : "l"(p));
    return a;
}
__device__ __forceinline__ void cpa16(uint32_t s, const void* g) {
    asm volatile("cp.async.ca.shared.global [%0], [%1], 16;" :: "r"(s), "l"(g));
}
#define CP_COMMIT() asm volatile("cp.async.commit_group;" ::: "memory")
#define CP_WAIT1()  asm volatile("cp.async.wait_group 1;" ::: "memory")

__device__ __forceinline__ void ldsm4(uint32_t& r0, uint32_t& r1,
                                      uint32_t& r2, uint32_t& r3, uint32_t a) {
    asm volatile("ldmatrix.sync.aligned.m8n8.x4.shared.b16 {%0,%1,%2,%3}, [%4];"
                 : "=r"(r0), "=r"(r1), "=r"(r2), "=r"(r3) : "r"(a));
}

__device__ __forceinline__ void mma16(float d[4], uint32_t a0, uint32_t a1,
                                      uint32_t a2, uint32_t a3,
                                      uint32_t b0, uint32_t b1) {
    asm volatile(
        "mma.sync.aligned.m16n8k16.row.col.f32.f16.f16.f32 "
        "{%0,%1,%2,%3}, {%4,%5,%6,%7}, {%8,%9}, {%0,%1,%2,%3};"
        : "+f"(d[0]), "+f"(d[1]), "+f"(d[2]), "+f"(d[3])
        : "r"(a0), "r"(a1), "r"(a2), "r"(a3), "r"(b0), "r"(b1));
}

// ================= prep kernels ============================================
__global__ __launch_bounds__(256) void cvt_x(const float* __restrict__ x) {
    int i = blockIdx.x * 256 + threadIdx.x;
    float4 v = ((const float4*)x)[i];
    uint2 o;
    o.x = h2u(v.x, v.y);
    o.y = h2u(v.z, v.w);
    ((uint2*)g_xh)[i] = o;
}

__global__ __launch_bounds__(256) void cvtT_w(
    const float* __restrict__ W0, const float* __restrict__ W1,
    const float* __restrict__ W2, const float* __restrict__ W3)
{
    __shared__ float t[32][33];
    const float* src = (blockIdx.z == 0) ? W0 : (blockIdx.z == 1) ? W1
                     : (blockIdx.z == 2) ? W2 : W3;
    __half* dst = g_wh + (size_t)blockIdx.z * DM * DM;
    int bk = blockIdx.y * 32, bn = blockIdx.x * 32;
    int tx = threadIdx.x & 31, ty = threadIdx.x >> 5;
#pragma unroll
    for (int i = 0; i < 4; i++)
        t[ty + 8 * i][tx] = src[(size_t)(bk + ty + 8 * i) * DM + bn + tx];
    __syncthreads();
#pragma unroll
    for (int i = 0; i < 4; i++)
        dst[(size_t)(bn + ty + 8 * i) * DM + bk + tx] =
            __float2half_rn(t[tx][ty + 8 * i]);
}

// ====== fp16 GEMM v3: 4 warps x (64x64), k-chunk 64, 2-stage cp.async ======
#define GBM 128
#define GBN 128
#define GBK 64
#define GP  72                         // pitch in halfs (144 B)
#define GTILE_H (128 * GP)             // 9216 halfs
#define GSTAGE 2
#define GSMEM (GSTAGE * 2 * GTILE_H * 2)   // 73728 B

// MODE 0: fused QKV (Q prescaled; V transposed to g_vth)  MODE 1: final
template<int MODE>
__global__ __launch_bounds__(128, 2) void gemm_h(
    const __half* __restrict__ A, const __half* __restrict__ BtBase,
    float* __restrict__ Cf, const float* __restrict__ bias)
{
    extern __shared__ __half gsmh[];

    const int tid = threadIdx.x;
    const int warp = tid >> 5, lane = tid & 31;
    const int g = lane >> 2, t = lane & 3;
    const int wm = (warp >> 1) * 64;
    const int wn = (warp & 1) * 64;
    const int m0 = blockIdx.y * GBM;
    const int n_glob = blockIdx.x * GBN;

    const __half* Bt = BtBase + (size_t)n_glob * DM;

    const int lr = lane & 7;
    const int lqA = lane >> 3;
    const uint32_t lmA = (uint32_t)((((lqA & 1) * 8 + lr) * GP + (lqA >> 1) * 8) * 2);
    const uint32_t lmB = (uint32_t)(((((lqA >> 1) & 1) * 8 + lr) * GP + (lqA & 1) * 8) * 2);

    // global->smem: tile is 128 rows x 64 halfs = 1024 chunks; 8 per thread
    int lrow[8], lc8[8];
#pragma unroll
    for (int it = 0; it < 8; it++) {
        int idx = tid + it * 128;
        lrow[it] = idx >> 3;            // 0..127
        lc8[it]  = (idx & 7) << 3;      // 0..56
    }
    const uint32_t sbase = smem_u32(gsmh);

#pragma unroll
    for (int st = 0; st < GSTAGE; st++) {
        int kt = st * GBK;
        uint32_t sa = sbase + st * 2 * GTILE_H * 2;
        uint32_t sb = sa + GTILE_H * 2;
#pragma unroll
        for (int it = 0; it < 8; it++) {
            cpa16(sa + (lrow[it] * GP + lc8[it]) * 2,
                  &A[(size_t)(m0 + lrow[it]) * DM + kt + lc8[it]]);
            cpa16(sb + (lrow[it] * GP + lc8[it]) * 2,
                  &Bt[(size_t)lrow[it] * DM + kt + lc8[it]]);
        }
        CP_COMMIT();
    }

    float acc[4][8][4] = {};

    const int NK = DM / GBK;   // 16
    for (int i = 0; i < NK; i++) {
        CP_WAIT1();
        __syncthreads();
        const int st = i & 1;
        const uint32_t aA = sbase + st * 2 * GTILE_H * 2;
        const uint32_t aB = aA + GTILE_H * 2;

#pragma unroll
        for (int ks = 0; ks < 4; ks++) {
            const int k16 = ks * 16;
            uint32_t af[4][4];
#pragma unroll
            for (int mt = 0; mt < 4; mt++)
                ldsm4(af[mt][0], af[mt][1], af[mt][2], af[mt][3],
                      aA + (uint32_t)(((wm + mt * 16) * GP + k16) * 2) + lmA);
            uint32_t bf[2][4];
            ldsm4(bf[0][0], bf[0][1], bf[0][2], bf[0][3],
                  aB + (uint32_t)((wn * GP + k16) * 2) + lmB);
#pragma unroll
            for (int ntp = 0; ntp < 4; ntp++) {
                if (ntp + 1 < 4)
                    ldsm4(bf[(ntp + 1) & 1][0], bf[(ntp + 1) & 1][1],
                          bf[(ntp + 1) & 1][2], bf[(ntp + 1) & 1][3],
                          aB + (uint32_t)(((wn + (ntp + 1) * 16) * GP + k16) * 2) + lmB);
                const uint32_t* B = bf[ntp & 1];
#pragma unroll
                for (int mt = 0; mt < 4; mt++) {
                    mma16(acc[mt][2 * ntp], af[mt][0], af[mt][1], af[mt][2],
                          af[mt][3], B[0], B[1]);
                    mma16(acc[mt][2 * ntp + 1], af[mt][0], af[mt][1], af[mt][2],
                          af[mt][3], B[2], B[3]);
                }
            }
        }
        __syncthreads();

        if (i + GSTAGE < NK) {
            int kt = (i + GSTAGE) * GBK;
            uint32_t sa = sbase + st * 2 * GTILE_H * 2;
            uint32_t sb = sa + GTILE_H * 2;
#pragma unroll
            for (int it = 0; it < 8; it++) {
                cpa16(sa + (lrow[it] * GP + lc8[it]) * 2,
                      &A[(size_t)(m0 + lrow[it]) * DM + kt + lc8[it]]);
                cpa16(sb + (lrow[it] * GP + lc8[it]) * 2,
                      &Bt[(size_t)lrow[it] * DM + kt + lc8[it]]);
            }
        }
        CP_COMMIT();
    }

    if (MODE == 0) {
        int mat = n_glob >> 10;               // 0=Q, 1=K, 2=V
        int c0 = n_glob & 1023;
        if (mat < 2) {
            __half* C = mat ? g_kh : g_qh;
            const float s = mat ? 1.0f : 0.18033688f;  // 0.125*log2(e)
#pragma unroll
            for (int mt = 0; mt < 4; mt++) {
                int r0 = m0 + wm + mt * 16 + g;
#pragma unroll
                for (int nt = 0; nt < 8; nt++) {
                    int col = c0 + wn + nt * 8 + 2 * t;
                    *(uint32_t*)&C[(size_t)r0 * DM + col] =
                        h2u(acc[mt][nt][0] * s, acc[mt][nt][1] * s);
                    *(uint32_t*)&C[(size_t)(r0 + 8) * DM + col] =
                        h2u(acc[mt][nt][2] * s, acc[mt][nt][3] * s);
                }
            }
        } else {
#pragma unroll
            for (int mt = 0; mt < 4; mt++) {
                int r0 = m0 + wm + mt * 16 + g;
#pragma unroll
                for (int nt = 0; nt < 8; nt++) {
                    int dcol = c0 + wn + nt * 8 + 2 * t;
                    int h = dcol >> 6, d = dcol & 63;
#pragma unroll
                    for (int rr = 0; rr < 2; rr++) {
                        int tok = r0 + rr * 8;
                        size_t base = ((size_t)((tok >> 11) * NHEADS + h) * HD + d)
                                      * SEQ + (tok & (SEQ - 1));
                        g_vth[base] = __float2half_rn(acc[mt][nt][rr * 2 + 0]);
                        g_vth[base + SEQ] = __float2half_rn(acc[mt][nt][rr * 2 + 1]);
                    }
                }
            }
        }
    } else {
#pragma unroll
        for (int mt = 0; mt < 4; mt++) {
            int r0 = m0 + wm + mt * 16 + g;
#pragma unroll
            for (int nt = 0; nt < 8; nt++) {
                int col = n_glob + wn + nt * 8 + 2 * t;
                float bv0 = bias[col], bv1 = bias[col + 1];
                *(float2*)&Cf[(size_t)r0 * DM + col] =
                    make_float2(acc[mt][nt][0] + bv0, acc[mt][nt][1] + bv1);
                *(float2*)&Cf[(size_t)(r0 + 8) * DM + col] =
                    make_float2(acc[mt][nt][2] + bv0, acc[mt][nt][3] + bv1);
            }
        }
    }
}

// ====== flash attention v6: 128-key loaded tiles, two 64-key sub-passes ====
// One barrier pair / cp.async epoch per 128 keys (half the sync epochs).
// 4 warps x 32 queries, fixed-max softmax, P in registers.
#define QBLK 128
#define KT   128                      // keys per loaded tile
#define KP   72                       // K tile pitch (d=64 + pad)
#define VPP  136                      // V tile pitch (keys=128 + pad)
#define KTILE_H (KT * KP)             // 9216 halfs
#define VTILE_H (64 * VPP)            // 8704 halfs
#define ASMEM ((2 * KTILE_H + 2 * VTILE_H) * 2)   // 71680 B

__global__ __launch_bounds__(128, 2) void attn_h()
{
    extern __shared__ __half smh[];
    __half* Ksb = smh;                    // [2][128][KP]  rows = key
    __half* Vsb = smh + 2 * KTILE_H;      // [2][64][VPP]  rows = d

    const int qt = gridDim.x - 1 - blockIdx.x;   // heavy blocks first
    const int h = blockIdx.y, b = blockIdx.z;
    const int tid = threadIdx.x;
    const int warp = tid >> 5, lane = tid & 31;
    const int g = lane >> 2, t = lane & 3;
    const int q0 = qt * QBLK;
    const int qrow = warp * 32;

    const __half* kgl = g_kh + (size_t)b * SEQ * DM + (size_t)h * HD;
    const __half* vtgl = g_vth + (size_t)(b * NHEADS + h) * HD * SEQ;

    const uint32_t skb = smem_u32(Ksb);
    const uint32_t svb = smem_u32(Vsb);

    const int lr = lane & 7, lq = lane >> 3;
    const uint32_t lmK = (uint32_t)(((((lq >> 1) & 1) * 8 + lr) * KP + (lq & 1) * 8) * 2);
    const uint32_t lmV = (uint32_t)(((((lq >> 1) & 1) * 8 + lr) * VPP + (lq & 1) * 8) * 2);

    const int NT = qt + 1;   // 128-key tiles covering [0, q0+128)

    // prefetch tile 0: K 128x64 (8 iters), V 64x128 (8 iters)
    {
#pragma unroll
        for (int it = 0; it < 8; it++) {
            int idx = tid + it * 128;
            int krow = idx >> 3, kc8 = (idx & 7) << 3;
            cpa16(skb + (krow * KP + kc8) * 2, &kgl[(size_t)krow * DM + kc8]);
            int vrow = idx >> 4, vc8 = (idx & 15) << 3;
            cpa16(svb + (vrow * VPP + vc8) * 2, &vtgl[(size_t)vrow * SEQ + vc8]);
        }
        CP_COMMIT();
    }

    // hoist Q fragments (Q prescaled by 0.125*log2e)
    uint32_t qf[2][4][4];
#pragma unroll
    for (int mt = 0; mt < 2; mt++) {
        const __half* qb = g_qh + (size_t)b * SEQ * DM + (size_t)h * HD
                         + (size_t)(q0 + qrow + mt * 16 + g) * DM;
#pragma unroll
        for (int ks = 0; ks < 4; ks++) {
            int k16 = ks * 16;
            qf[mt][ks][0] = *(const uint32_t*)(qb + k16 + 2 * t);
            qf[mt][ks][1] = *(const uint32_t*)(qb + 8 * DM + k16 + 2 * t);
            qf[mt][ks][2] = *(const uint32_t*)(qb + k16 + 2 * t + 8);
            qf[mt][ks][3] = *(const uint32_t*)(qb + 8 * DM + k16 + 2 * t + 8);
        }
    }

    float l[2][2] = {};
    float oacc[2][8][4] = {};

    for (int jt = 0; jt < NT; jt++) {
        if (jt + 1 < NT) {
            const int nk0 = (jt + 1) * KT;
            const int nb = (jt + 1) & 1;
            uint32_t ka = skb + nb * KTILE_H * 2;
            uint32_t va = svb + nb * VTILE_H * 2;
#pragma unroll
            for (int it = 0; it < 8; it++) {
                int idx = tid + it * 128;
                int krow = idx >> 3, kc8 = (idx & 7) << 3;
                cpa16(ka + (krow * KP + kc8) * 2,
                      &kgl[(size_t)(nk0 + krow) * DM + kc8]);
                int vrow = idx >> 4, vc8 = (idx & 15) << 3;
                cpa16(va + (vrow * VPP + vc8) * 2,
                      &vtgl[(size_t)vrow * SEQ + nk0 + vc8]);
            }
        }
        CP_COMMIT();
        CP_WAIT1();
        __syncthreads();

        const uint32_t ksaT = skb + (jt & 1) * KTILE_H * 2;
        const uint32_t vsaT = svb + (jt & 1) * VTILE_H * 2;
        const bool diag = (jt == qt);

        // two 64-key sub-passes over the loaded 128-key tile
#pragma unroll
        for (int sp = 0; sp < 2; sp++) {
            const uint32_t ksa = ksaT + (uint32_t)(sp * 64 * KP * 2);
            const uint32_t vsa = vsaT + (uint32_t)(sp * 64 * 2);
            const int k0 = jt * KT + sp * 64;

            // ---- S = Q' @ K^T ----
            float sacc[2][8][4] = {};
            {
                uint32_t kb[2][4];
                ldsm4(kb[0][0], kb[0][1], kb[0][2], kb[0][3], ksa + lmK);
#pragma unroll
                for (int it = 0; it < 16; it++) {
                    const int ks = it >> 2, ntp = it & 3;
                    if (it + 1 < 16) {
                        const int ks2 = (it + 1) >> 2, ntp2 = (it + 1) & 3;
                        ldsm4(kb[(it + 1) & 1][0], kb[(it + 1) & 1][1],
                              kb[(it + 1) & 1][2], kb[(it + 1) & 1][3],
                              ksa + (uint32_t)((ntp2 * 16 * KP + ks2 * 16) * 2) + lmK);
                    }
                    const uint32_t* B = kb[it & 1];
#pragma unroll
                    for (int mt = 0; mt < 2; mt++) {
                        mma16(sacc[mt][2 * ntp], qf[mt][ks][0], qf[mt][ks][1],
                              qf[mt][ks][2], qf[mt][ks][3], B[0], B[1]);
                        mma16(sacc[mt][2 * ntp + 1], qf[mt][ks][0], qf[mt][ks][1],
                              qf[mt][ks][2], qf[mt][ks][3], B[2], B[3]);
                    }
                }
            }

            // pre-issue first V fragment
            uint32_t vb[2][4];
            ldsm4(vb[0][0], vb[0][1], vb[0][2], vb[0][3], vsa + lmV);

            if (diag) {
#pragma unroll
                for (int mt = 0; mt < 2; mt++) {
                    const int r0 = q0 + qrow + mt * 16 + g, r1 = r0 + 8;
#pragma unroll
                    for (int nt = 0; nt < 8; nt++) {
                        int c0 = k0 + nt * 8 + 2 * t, c1 = c0 + 1;
                        if (c0 > r0) sacc[mt][nt][0] = -1e30f;
                        if (c1 > r0) sacc[mt][nt][1] = -1e30f;
                        if (c0 > r1) sacc[mt][nt][2] = -1e30f;
                        if (c1 > r1) sacc[mt][nt][3] = -1e30f;
                    }
                }
            }

            // ---- fixed-max softmax: p = 2^s' ----
            uint32_t pf[2][8][2];
#pragma unroll
            for (int mt = 0; mt < 2; mt++)
#pragma unroll
                for (int nt = 0; nt < 8; nt++) {
                    uint32_t e0 = ex2h2(h2u(sacc[mt][nt][0], sacc[mt][nt][1]));
                    uint32_t e1 = ex2h2(h2u(sacc[mt][nt][2], sacc[mt][nt][3]));
                    pf[mt][nt][0] = e0;
                    pf[mt][nt][1] = e1;
                    float2 f0 = __half22float2(*(__half2*)&e0);
                    float2 f1 = __half22float2(*(__half2*)&e1);
                    l[mt][0] += f0.x + f0.y;
                    l[mt][1] += f1.x + f1.y;
                }

            // ---- O += P @ V ----
#pragma unroll
            for (int it = 0; it < 16; it++) {
                const int ksp = it >> 2, ntd = it & 3;
                if (it + 1 < 16) {
                    const int ksp2 = (it + 1) >> 2, ntd2 = (it + 1) & 3;
                    ldsm4(vb[(it + 1) & 1][0], vb[(it + 1) & 1][1],
                          vb[(it + 1) & 1][2], vb[(it + 1) & 1][3],
                          vsa + (uint32_t)((ntd2 * 16 * VPP + ksp2 * 16) * 2) + lmV);
                }
                const uint32_t* V = vb[it & 1];
#pragma unroll
                for (int mt = 0; mt < 2; mt++) {
                    mma16(oacc[mt][2 * ntd], pf[mt][2 * ksp][0], pf[mt][2 * ksp][1],
                          pf[mt][2 * ksp + 1][0], pf[mt][2 * ksp + 1][1], V[0], V[1]);
                    mma16(oacc[mt][2 * ntd + 1], pf[mt][2 * ksp][0], pf[mt][2 * ksp][1],
                          pf[mt][2 * ksp + 1][0], pf[mt][2 * ksp + 1][1], V[2], V[3]);
                }
            }
        }
        __syncthreads();
    }

    // final l reduction (4 lanes per row quad) and write
#pragma unroll
    for (int mt = 0; mt < 2; mt++) {
#pragma unroll
        for (int off = 1; off < 4; off <<= 1) {
            l[mt][0] += __shfl_xor_sync(0xffffffffu, l[mt][0], off);
            l[mt][1] += __shfl_xor_sync(0xffffffffu, l[mt][1], off);
        }
        const float inv0 = 1.f / l[mt][0], inv1 = 1.f / l[mt][1];
        __half* ctx = g_ctxh + (size_t)b * SEQ * DM + (size_t)h * HD;
        const int r0 = q0 + qrow + mt * 16 + g, r1 = r0 + 8;
#pragma unroll
        for (int nt = 0; nt < 8; nt++) {
            int c = nt * 8 + 2 * t;
            *(uint32_t*)&ctx[(size_t)r0 * DM + c] =
                h2u(oacc[mt][nt][0] * inv0, oacc[mt][nt][1] * inv0);
            *(uint32_t*)&ctx[(size_t)r1 * DM + c] =
                h2u(oacc[mt][nt][2] * inv1, oacc[mt][nt][3] * inv1);
        }
    }
}

// ---------------- launch ---------------------------------------------------
extern "C" void kernel_launch(void* const* d_in, const int* in_sizes, int n_in,
                              void* d_out, int out_size)
{
    const float* x  = (const float*)d_in[0];
    const float* Wq = (const float*)d_in[1];
    const float* Wk = (const float*)d_in[2];
    const float* Wv = (const float*)d_in[3];
    const float* Wo = (const float*)d_in[4];
    const float* bo = (const float*)d_in[5];
    float* out = (float*)d_out;

    __half *gxh, *gwh, *gctxh;
    cudaGetSymbolAddress((void**)&gxh, g_xh);
    cudaGetSymbolAddress((void**)&gwh, g_wh);
    cudaGetSymbolAddress((void**)&gctxh, g_ctxh);

    cvt_x<<<MTOT * DM / 4 / 256, 256>>>(x);
    cvtT_w<<<dim3(32, 32, 4), 256>>>(Wq, Wk, Wv, Wo);

    cudaFuncSetAttribute(gemm_h<0>,
                         cudaFuncAttributeMaxDynamicSharedMemorySize, GSMEM);
    cudaFuncSetAttribute(gemm_h<1>,
                         cudaFuncAttributeMaxDynamicSharedMemorySize, GSMEM);

    gemm_h<0><<<dim3(3 * DM / GBN, MTOT / GBM), 128, GSMEM>>>(
        gxh, gwh, nullptr, nullptr);

    cudaFuncSetAttribute(attn_h,
                         cudaFuncAttributeMaxDynamicSharedMemorySize, (int)ASMEM);
    attn_h<<<dim3(SEQ / QBLK, NHEADS, BATCH), 128, ASMEM>>>();

    gemm_h<1><<<dim3(DM / GBN, MTOT / GBM), 128, GSMEM>>>(
        gctxh, gwh + 3 * (size_t)DM * DM, out, bo);
}

// round 16
// speedup vs baseline: 1.0778x; 1.0778x over previous
#include <cuda_runtime.h>
#include <cuda_fp16.h>
#include <math.h>
#include <stdint.h>

#define BATCH  2
#define SEQ    2048
#define DM     1024
#define NHEADS 16
#define HD     64
#define MTOT   (BATCH * SEQ)   // 4096

// ---------------- scratch (static device globals; no runtime alloc) --------
__device__ __half g_xh [MTOT * DM];      // x, fp16
__device__ __half g_wh [4 * DM * DM];    // transposed weights [mat][N][K], fp16
__device__ __half g_qh [MTOT * DM];      // Q, PRESCALED by 0.125*log2(e)
__device__ __half g_kh [MTOT * DM];      // K [tok][dmodel]
__device__ __half g_vth[MTOT * DM];      // V transposed [b*h][d(64)][seq]
__device__ __half g_ctxh[MTOT * DM];     // attention output [tok][dmodel]

// ============================ helpers ======================================
__device__ __forceinline__ uint32_t h2u(float a, float b) {
    __half2 h = __floats2half2_rn(a, b);
    return *(uint32_t*)&h;
}
__device__ __forceinline__ uint32_t ex2h2(uint32_t x) {   // packed 2^x, fp16x2
    uint32_t r;
    asm("ex2.approx.f16x2 %0, %1;" : "=r"(r) : "r"(x));
    return r;
}
__device__ __forceinline__ uint32_t smem_u32(const void* p) {
    uint32_t a;
    asm("{ .reg .u64 t; cvta.to.shared.u64 t, %1; cvt.u32.u64 %0, t; }"
        : "=r"(a) : "l"(p));
    return a;
}
__device__ __forceinline__ void cpa16(uint32_t s, const void* g) {
    asm volatile("cp.async.ca.shared.global [%0], [%1], 16;" :: "r"(s), "l"(g));
}
#define CP_COMMIT() asm volatile("cp.async.commit_group;" ::: "memory")
#define CP_WAIT0()  asm volatile("cp.async.wait_group 0;" ::: "memory")
#define CP_WAIT2()  asm volatile("cp.async.wait_group 2;" ::: "memory")

__device__ __forceinline__ void ldsm4(uint32_t& r0, uint32_t& r1,
                                      uint32_t& r2, uint32_t& r3, uint32_t a) {
    asm volatile("ldmatrix.sync.aligned.m8n8.x4.shared.b16 {%0,%1,%2,%3}, [%4];"
                 : "=r"(r0), "=r"(r1), "=r"(r2), "=r"(r3) : "r"(a));
}

__device__ __forceinline__ void mma16(float d[4], uint32_t a0, uint32_t a1,
                                      uint32_t a2, uint32_t a3,
                                      uint32_t b0, uint32_t b1) {
    asm volatile(
        "mma.sync.aligned.m16n8k16.row.col.f32.f16.f16.f32 "
        "{%0,%1,%2,%3}, {%4,%5,%6,%7}, {%8,%9}, {%0,%1,%2,%3};"
        : "+f"(d[0]), "+f"(d[1]), "+f"(d[2]), "+f"(d[3])
        : "r"(a0), "r"(a1), "r"(a2), "r"(a3), "r"(b0), "r"(b1));
}

// ================= prep kernels ============================================
__global__ __launch_bounds__(256) void cvt_x(const float* __restrict__ x) {
    int i = blockIdx.x * 256 + threadIdx.x;
    float4 v = ((const float4*)x)[i];
    uint2 o;
    o.x = h2u(v.x, v.y);
    o.y = h2u(v.z, v.w);
    ((uint2*)g_xh)[i] = o;
}

__global__ __launch_bounds__(256) void cvtT_w(
    const float* __restrict__ W0, const float* __restrict__ W1,
    const float* __restrict__ W2, const float* __restrict__ W3)
{
    __shared__ float t[32][33];
    const float* src = (blockIdx.z == 0) ? W0 : (blockIdx.z == 1) ? W1
                     : (blockIdx.z == 2) ? W2 : W3;
    __half* dst = g_wh + (size_t)blockIdx.z * DM * DM;
    int bk = blockIdx.y * 32, bn = blockIdx.x * 32;
    int tx = threadIdx.x & 31, ty = threadIdx.x >> 5;
#pragma unroll
    for (int i = 0; i < 4; i++)
        t[ty + 8 * i][tx] = src[(size_t)(bk + ty + 8 * i) * DM + bn + tx];
    __syncthreads();
#pragma unroll
    for (int i = 0; i < 4; i++)
        dst[(size_t)(bn + ty + 8 * i) * DM + bk + tx] =
            __float2half_rn(t[tx][ty + 8 * i]);
}

// ====== fp16 GEMM (R14): 4 warps x (64x64), k-chunk 32, 3-stage cp.async ===
#define GBM 128
#define GBN 128
#define GBK 32
#define GP  40                         // pitch in halfs
#define GTILE_H (128 * GP)
#define GSTAGE 3
#define GSMEM (GSTAGE * 2 * GTILE_H * 2)   // 61440 B

// MODE 0: fused QKV (Q prescaled; V transposed to g_vth)  MODE 1: final
template<int MODE>
__global__ __launch_bounds__(128, 2) void gemm_h(
    const __half* __restrict__ A, const __half* __restrict__ BtBase,
    float* __restrict__ Cf, const float* __restrict__ bias)
{
    extern __shared__ __half gsmh[];

    const int tid = threadIdx.x;
    const int warp = tid >> 5, lane = tid & 31;
    const int g = lane >> 2, t = lane & 3;
    const int wm = (warp >> 1) * 64;
    const int wn = (warp & 1) * 64;
    const int m0 = blockIdx.y * GBM;
    const int n_glob = blockIdx.x * GBN;

    const __half* Bt = BtBase + (size_t)n_glob * DM;

    const int lr = lane & 7;
    const int lqA = lane >> 3;
    const uint32_t lmA = (uint32_t)((((lqA & 1) * 8 + lr) * GP + (lqA >> 1) * 8) * 2);
    const uint32_t lmB = (uint32_t)(((((lqA >> 1) & 1) * 8 + lr) * GP + (lqA & 1) * 8) * 2);

    int lrow[4], lc8[4];
#pragma unroll
    for (int it = 0; it < 4; it++) {
        int idx = tid + it * 128;
        lrow[it] = idx >> 2;
        lc8[it]  = (idx & 3) << 3;
    }
    const uint32_t sbase = smem_u32(gsmh);

#pragma unroll
    for (int st = 0; st < GSTAGE; st++) {
        int kt = st * GBK;
        uint32_t sa = sbase + st * 2 * GTILE_H * 2;
        uint32_t sb = sa + GTILE_H * 2;
#pragma unroll
        for (int it = 0; it < 4; it++) {
            cpa16(sa + (lrow[it] * GP + lc8[it]) * 2,
                  &A[(size_t)(m0 + lrow[it]) * DM + kt + lc8[it]]);
            cpa16(sb + (lrow[it] * GP + lc8[it]) * 2,
                  &Bt[(size_t)lrow[it] * DM + kt + lc8[it]]);
        }
        CP_COMMIT();
    }

    float acc[4][8][4] = {};

    const int NK = DM / GBK;   // 32
    for (int i = 0; i < NK; i++) {
        CP_WAIT2();
        __syncthreads();
        const int st = i % GSTAGE;
        const uint32_t aA = sbase + st * 2 * GTILE_H * 2;
        const uint32_t aB = aA + GTILE_H * 2;

#pragma unroll
        for (int ks = 0; ks < 2; ks++) {
            const int k16 = ks * 16;
            uint32_t af[4][4];
#pragma unroll
            for (int mt = 0; mt < 4; mt++)
                ldsm4(af[mt][0], af[mt][1], af[mt][2], af[mt][3],
                      aA + (uint32_t)(((wm + mt * 16) * GP + k16) * 2) + lmA);
            uint32_t bf[2][4];
            ldsm4(bf[0][0], bf[0][1], bf[0][2], bf[0][3],
                  aB + (uint32_t)((wn * GP + k16) * 2) + lmB);
#pragma unroll
            for (int ntp = 0; ntp < 4; ntp++) {
                if (ntp + 1 < 4)
                    ldsm4(bf[(ntp + 1) & 1][0], bf[(ntp + 1) & 1][1],
                          bf[(ntp + 1) & 1][2], bf[(ntp + 1) & 1][3],
                          aB + (uint32_t)(((wn + (ntp + 1) * 16) * GP + k16) * 2) + lmB);
                const uint32_t* B = bf[ntp & 1];
#pragma unroll
                for (int mt = 0; mt < 4; mt++) {
                    mma16(acc[mt][2 * ntp], af[mt][0], af[mt][1], af[mt][2],
                          af[mt][3], B[0], B[1]);
                    mma16(acc[mt][2 * ntp + 1], af[mt][0], af[mt][1], af[mt][2],
                          af[mt][3], B[2], B[3]);
                }
            }
        }
        __syncthreads();

        if (i + GSTAGE < NK) {
            int kt = (i + GSTAGE) * GBK;
            uint32_t sa = sbase + st * 2 * GTILE_H * 2;
            uint32_t sb = sa + GTILE_H * 2;
#pragma unroll
            for (int it = 0; it < 4; it++) {
                cpa16(sa + (lrow[it] * GP + lc8[it]) * 2,
                      &A[(size_t)(m0 + lrow[it]) * DM + kt + lc8[it]]);
                cpa16(sb + (lrow[it] * GP + lc8[it]) * 2,
                      &Bt[(size_t)lrow[it] * DM + kt + lc8[it]]);
            }
        }
        CP_COMMIT();
    }

    if (MODE == 0) {
        int mat = n_glob >> 10;               // 0=Q, 1=K, 2=V
        int c0 = n_glob & 1023;
        if (mat < 2) {
            __half* C = mat ? g_kh : g_qh;
            const float s = mat ? 1.0f : 0.18033688f;  // 0.125*log2(e)
#pragma unroll
            for (int mt = 0; mt < 4; mt++) {
                int r0 = m0 + wm + mt * 16 + g;
#pragma unroll
                for (int nt = 0; nt < 8; nt++) {
                    int col = c0 + wn + nt * 8 + 2 * t;
                    *(uint32_t*)&C[(size_t)r0 * DM + col] =
                        h2u(acc[mt][nt][0] * s, acc[mt][nt][1] * s);
                    *(uint32_t*)&C[(size_t)(r0 + 8) * DM + col] =
                        h2u(acc[mt][nt][2] * s, acc[mt][nt][3] * s);
                }
            }
        } else {
#pragma unroll
            for (int mt = 0; mt < 4; mt++) {
                int r0 = m0 + wm + mt * 16 + g;
#pragma unroll
                for (int nt = 0; nt < 8; nt++) {
                    int dcol = c0 + wn + nt * 8 + 2 * t;
                    int h = dcol >> 6, d = dcol & 63;
#pragma unroll
                    for (int rr = 0; rr < 2; rr++) {
                        int tok = r0 + rr * 8;
                        size_t base = ((size_t)((tok >> 11) * NHEADS + h) * HD + d)
                                      * SEQ + (tok & (SEQ - 1));
                        g_vth[base] = __float2half_rn(acc[mt][nt][rr * 2 + 0]);
                        g_vth[base + SEQ] = __float2half_rn(acc[mt][nt][rr * 2 + 1]);
                    }
                }
            }
        }
    } else {
#pragma unroll
        for (int mt = 0; mt < 4; mt++) {
            int r0 = m0 + wm + mt * 16 + g;
#pragma unroll
            for (int nt = 0; nt < 8; nt++) {
                int col = n_glob + wn + nt * 8 + 2 * t;
                float bv0 = bias[col], bv1 = bias[col + 1];
                *(float2*)&Cf[(size_t)r0 * DM + col] =
                    make_float2(acc[mt][nt][0] + bv0, acc[mt][nt][1] + bv1);
                *(float2*)&Cf[(size_t)(r0 + 8) * DM + col] =
                    make_float2(acc[mt][nt][2] + bv0, acc[mt][nt][3] + bv1);
            }
        }
    }
}

// ====== flash attention v7: R13/R14 shape, ONE barrier per tile ============
// Loop reordered to wait0 -> sync -> prefetch(jt+1) -> compute(jt): the
// prefetch into buf (jt+1)&1 happens only after every warp finished reading
// it (they all passed this tile's barrier), so the trailing barrier goes.
#define QBLK 128
#define AP 72
#define KTILE_H (64 * AP)
#define ASMEM (4 * KTILE_H * 2)      // 36864 B

__global__ __launch_bounds__(128, 2) void attn_h()
{
    extern __shared__ __half smh[];
    __half* Ksb = smh;                    // [2][64][AP] (rows = key)
    __half* Vsb = smh + 2 * KTILE_H;      // [2][64][AP] (rows = d)

    const int qt = gridDim.x - 1 - blockIdx.x;   // heavy blocks first
    const int h = blockIdx.y, b = blockIdx.z;
    const int tid = threadIdx.x;
    const int warp = tid >> 5, lane = tid & 31;
    const int g = lane >> 2, t = lane & 3;
    const int q0 = qt * QBLK;
    const int qrow = warp * 32;

    const __half* kgl = g_kh + (size_t)b * SEQ * DM + (size_t)h * HD;
    const __half* vtgl = g_vth + (size_t)(b * NHEADS + h) * HD * SEQ;

    const uint32_t skb = smem_u32(Ksb);
    const uint32_t svb = smem_u32(Vsb);

    const int lr = lane & 7, lq = lane >> 3;
    const uint32_t lmB = (uint32_t)(((((lq >> 1) & 1) * 8 + lr) * AP + (lq & 1) * 8) * 2);

    const int NT = 2 * qt + 2;

    // prologue: prefetch tile 0 into buffer 0
    {
#pragma unroll
        for (int it = 0; it < 4; it++) {
            int idx = tid + it * 128;
            int row = idx >> 3, c8 = (idx & 7) << 3;
            cpa16(skb + (row * AP + c8) * 2, &kgl[(size_t)row * DM + c8]);
            cpa16(svb + (row * AP + c8) * 2, &vtgl[(size_t)row * SEQ + c8]);
        }
        CP_COMMIT();
    }

    // hoist Q fragments (Q prescaled by 0.125*log2e)
    uint32_t qf[2][4][4];
#pragma unroll
    for (int mt = 0; mt < 2; mt++) {
        const __half* qb = g_qh + (size_t)b * SEQ * DM + (size_t)h * HD
                         + (size_t)(q0 + qrow + mt * 16 + g) * DM;
#pragma unroll
        for (int ks = 0; ks < 4; ks++) {
            int k16 = ks * 16;
            qf[mt][ks][0] = *(const uint32_t*)(qb + k16 + 2 * t);
            qf[mt][ks][1] = *(const uint32_t*)(qb + 8 * DM + k16 + 2 * t);
            qf[mt][ks][2] = *(const uint32_t*)(qb + k16 + 2 * t + 8);
            qf[mt][ks][3] = *(const uint32_t*)(qb + 8 * DM + k16 + 2 * t + 8);
        }
    }

    float l[2][2] = {};
    float oacc[2][8][4] = {};

    for (int jt = 0; jt < NT; jt++) {
        // drain this tile's transfers, make all threads' data visible
        CP_WAIT0();
        __syncthreads();

        // prefetch next tile (safe: every warp has finished reading that
        // buffer — they all just passed the barrier above)
        if (jt + 1 < NT) {
            const int nk0 = (jt + 1) * 64;
            const int nb = (jt + 1) & 1;
            uint32_t ka = skb + nb * KTILE_H * 2;
            uint32_t va = svb + nb * KTILE_H * 2;
#pragma unroll
            for (int it = 0; it < 4; it++) {
                int idx = tid + it * 128;
                int row = idx >> 3, c8 = (idx & 7) << 3;
                cpa16(ka + (row * AP + c8) * 2,
                      &kgl[(size_t)(nk0 + row) * DM + c8]);
                cpa16(va + (row * AP + c8) * 2,
                      &vtgl[(size_t)row * SEQ + nk0 + c8]);
            }
            CP_COMMIT();
        }

        const uint32_t ksa = skb + (jt & 1) * KTILE_H * 2;
        const uint32_t vsa = svb + (jt & 1) * KTILE_H * 2;
        const int k0 = jt * 64;

        // ---- S = Q' @ K^T, each K frag feeds both m-tiles ----
        float sacc[2][8][4] = {};
        {
            uint32_t kb[2][4];
            ldsm4(kb[0][0], kb[0][1], kb[0][2], kb[0][3], ksa + lmB);
#pragma unroll
            for (int it = 0; it < 16; it++) {
                const int ks = it >> 2, ntp = it & 3;
                if (it + 1 < 16) {
                    const int ks2 = (it + 1) >> 2, ntp2 = (it + 1) & 3;
                    ldsm4(kb[(it + 1) & 1][0], kb[(it + 1) & 1][1],
                          kb[(it + 1) & 1][2], kb[(it + 1) & 1][3],
                          ksa + (uint32_t)((ntp2 * 16 * AP + ks2 * 16) * 2) + lmB);
                }
                const uint32_t* B = kb[it & 1];
#pragma unroll
                for (int mt = 0; mt < 2; mt++) {
                    mma16(sacc[mt][2 * ntp], qf[mt][ks][0], qf[mt][ks][1],
                          qf[mt][ks][2], qf[mt][ks][3], B[0], B[1]);
                    mma16(sacc[mt][2 * ntp + 1], qf[mt][ks][0], qf[mt][ks][1],
                          qf[mt][ks][2], qf[mt][ks][3], B[2], B[3]);
                }
            }
        }

        // pre-issue first V fragment
        uint32_t vb[2][4];
        ldsm4(vb[0][0], vb[0][1], vb[0][2], vb[0][3], vsa + lmB);

        if (jt >= 2 * qt) {   // diagonal band
#pragma unroll
            for (int mt = 0; mt < 2; mt++) {
                const int r0 = q0 + qrow + mt * 16 + g, r1 = r0 + 8;
#pragma unroll
                for (int nt = 0; nt < 8; nt++) {
                    int c0 = k0 + nt * 8 + 2 * t, c1 = c0 + 1;
                    if (c0 > r0) sacc[mt][nt][0] = -1e30f;
                    if (c1 > r0) sacc[mt][nt][1] = -1e30f;
                    if (c0 > r1) sacc[mt][nt][2] = -1e30f;
                    if (c1 > r1) sacc[mt][nt][3] = -1e30f;
                }
            }
        }

        // ---- fixed-max softmax: p = 2^s' directly ----
        uint32_t pf[2][8][2];
#pragma unroll
        for (int mt = 0; mt < 2; mt++)
#pragma unroll
            for (int nt = 0; nt < 8; nt++) {
                uint32_t e0 = ex2h2(h2u(sacc[mt][nt][0], sacc[mt][nt][1]));
                uint32_t e1 = ex2h2(h2u(sacc[mt][nt][2], sacc[mt][nt][3]));
                pf[mt][nt][0] = e0;
                pf[mt][nt][1] = e1;
                float2 f0 = __half22float2(*(__half2*)&e0);
                float2 f1 = __half22float2(*(__half2*)&e1);
                l[mt][0] += f0.x + f0.y;
                l[mt][1] += f1.x + f1.y;
            }

        // ---- O += P @ V, each V frag feeds both m-tiles ----
#pragma unroll
        for (int it = 0; it < 16; it++) {
            const int ksp = it >> 2, ntd = it & 3;
            if (it + 1 < 16) {
                const int ksp2 = (it + 1) >> 2, ntd2 = (it + 1) & 3;
                ldsm4(vb[(it + 1) & 1][0], vb[(it + 1) & 1][1],
                      vb[(it + 1) & 1][2], vb[(it + 1) & 1][3],
                      vsa + (uint32_t)((ntd2 * 16 * AP + ksp2 * 16) * 2) + lmB);
            }
            const uint32_t* V = vb[it & 1];
#pragma unroll
            for (int mt = 0; mt < 2; mt++) {
                mma16(oacc[mt][2 * ntd], pf[mt][2 * ksp][0], pf[mt][2 * ksp][1],
                      pf[mt][2 * ksp + 1][0], pf[mt][2 * ksp + 1][1], V[0], V[1]);
                mma16(oacc[mt][2 * ntd + 1], pf[mt][2 * ksp][0], pf[mt][2 * ksp][1],
                      pf[mt][2 * ksp + 1][0], pf[mt][2 * ksp + 1][1], V[2], V[3]);
            }
        }
        // (no trailing barrier — see loop-head comment)
    }

    // final l reduction (4 lanes per row quad) and write
#pragma unroll
    for (int mt = 0; mt < 2; mt++) {
#pragma unroll
        for (int off = 1; off < 4; off <<= 1) {
            l[mt][0] += __shfl_xor_sync(0xffffffffu, l[mt][0], off);
            l[mt][1] += __shfl_xor_sync(0xffffffffu, l[mt][1], off);
        }
        const float inv0 = 1.f / l[mt][0], inv1 = 1.f / l[mt][1];
        __half* ctx = g_ctxh + (size_t)b * SEQ * DM + (size_t)h * HD;
        const int r0 = q0 + qrow + mt * 16 + g, r1 = r0 + 8;
#pragma unroll
        for (int nt = 0; nt < 8; nt++) {
            int c = nt * 8 + 2 * t;
            *(uint32_t*)&ctx[(size_t)r0 * DM + c] =
                h2u(oacc[mt][nt][0] * inv0, oacc[mt][nt][1] * inv0);
            *(uint32_t*)&ctx[(size_t)r1 * DM + c] =
                h2u(oacc[mt][nt][2] * inv1, oacc[mt][nt][3] * inv1);
        }
    }
}

// ---------------- launch ---------------------------------------------------
extern "C" void kernel_launch(void* const* d_in, const int* in_sizes, int n_in,
                              void* d_out, int out_size)
{
    const float* x  = (const float*)d_in[0];
    const float* Wq = (const float*)d_in[1];
    const float* Wk = (const float*)d_in[2];
    const float* Wv = (const float*)d_in[3];
    const float* Wo = (const float*)d_in[4];
    const float* bo = (const float*)d_in[5];
    float* out = (float*)d_out;

    __half *gxh, *gwh, *gctxh;
    cudaGetSymbolAddress((void**)&gxh, g_xh);
    cudaGetSymbolAddress((void**)&gwh, g_wh);
    cudaGetSymbolAddress((void**)&gctxh, g_ctxh);

    cvt_x<<<MTOT * DM / 4 / 256, 256>>>(x);
    cvtT_w<<<dim3(32, 32, 4), 256>>>(Wq, Wk, Wv, Wo);

    cudaFuncSetAttribute(gemm_h<0>,
                         cudaFuncAttributeMaxDynamicSharedMemorySize, GSMEM);
    cudaFuncSetAttribute(gemm_h<1>,
                         cudaFuncAttributeMaxDynamicSharedMemorySize, GSMEM);

    gemm_h<0><<<dim3(3 * DM / GBN, MTOT / GBM), 128, GSMEM>>>(
        gxh, gwh, nullptr, nullptr);

    cudaFuncSetAttribute(attn_h,
                         cudaFuncAttributeMaxDynamicSharedMemorySize, (int)ASMEM);
    attn_h<<<dim3(SEQ / QBLK, NHEADS, BATCH), 128, ASMEM>>>();

    gemm_h<1><<<dim3(DM / GBN, MTOT / GBM), 128, GSMEM>>>(
        gctxh, gwh + 3 * (size_t)DM * DM, out, bo);
}